// round 7
// baseline (speedup 1.0000x reference)
#include <cuda_runtime.h>

// WindowMSA fused kernel: one CTA per window (4096 windows).
// Per window: qkv = x @ Wqkv^T (per head), attn = softmax(qk^T*scale + bias),
// out_h = attn @ v, y = out @ Wproj^T. Everything staged in SMEM, fp32 FFMA.

#define NTOK 64
#define CDIM 256
#define NHEAD 8
#define HDIM 32
#define SCALE 0.17677669529663687f   // 1/sqrt(32)

// ---- shared memory layout (in floats) ----
#define OFF_X    0
#define SZ_X     (64*256)            // x tile, row-major [64][256]
#define OFF_OP   (OFF_X + SZ_X)      // pre-proj output [64][260] (pad 4)
#define OP_LD    260
#define SZ_OP    (64*OP_LD)
#define OFF_Q    (OFF_OP + SZ_OP)    // q [64][36]
#define QK_LD    36
#define SZ_Q     (64*QK_LD)
#define OFF_K    (OFF_Q + SZ_Q)      // k [64][36]
#define SZ_K     (64*QK_LD)
#define OFF_VT   (OFF_K + SZ_K)      // v transposed [32][68]
#define VT_LD    68
#define SZ_VT    (32*VT_LD)
#define OFF_S    (OFF_VT + SZ_VT)    // scores / probs [64][68]
#define S_LD     68
#define SZ_S     (64*S_LD)
#define OFF_WT   (OFF_S + SZ_S)      // weight K-tile, up to [128][33]
#define WT_LD    33
#define SZ_WT    (128*WT_LD)
#define OFF_RPE  (OFF_WT + SZ_WT)    // rpe table [225*8]
#define SZ_RPE   (225*8)
#define OFF_RINV (OFF_RPE + SZ_RPE)  // 1/rowsum [64]
#define SZ_RINV  64
#define OFF_IDX  (OFF_RINV + SZ_RINV) // rpe_idx as uchar[4096] = 1024 floats
#define SZ_IDX_F 1024
#define SMEM_FLOATS (OFF_IDX + SZ_IDX_F)
#define SMEM_BYTES  (SMEM_FLOATS * 4)   // 205,088 B

__global__ void __launch_bounds__(256, 1)
wmsa_fused_kernel(const float* __restrict__ x,
                  const float* __restrict__ Wqkv,
                  const float* __restrict__ Wproj,
                  const float* __restrict__ rpe,
                  const int*   __restrict__ rpe_idx,
                  float*       __restrict__ y)
{
    extern __shared__ float sm[];
    float* sm_x    = sm + OFF_X;
    float* sm_op   = sm + OFF_OP;
    float* sm_q    = sm + OFF_Q;
    float* sm_k    = sm + OFF_K;
    float* sm_vt   = sm + OFF_VT;
    float* sm_s    = sm + OFF_S;
    float* sm_wt   = sm + OFF_WT;
    float* sm_rpe  = sm + OFF_RPE;
    float* sm_rinv = sm + OFF_RINV;
    unsigned char* sm_idx = (unsigned char*)(sm + OFF_IDX);

    const int tid = threadIdx.x;
    const int win = blockIdx.x;
    const int tg  = tid >> 4;   // 0..15 -> token group (4 rows)
    const int lg  = tid & 15;   // 0..15 -> column group
    const int t0  = tg * 4;

    // ---- stage x (float4, coalesced) ----
    {
        const float4* xg = reinterpret_cast<const float4*>(x + (size_t)win * (64 * 256));
        float4* xs4 = reinterpret_cast<float4*>(sm_x);
        #pragma unroll
        for (int i = 0; i < 16; ++i)
            xs4[tid + i * 256] = xg[tid + i * 256];
    }
    // ---- stage rpe table + rpe_idx (as uint8; values < 225) ----
    for (int i = tid; i < 225 * 8; i += 256)
        sm_rpe[i] = rpe[i];
    #pragma unroll
    for (int i = 0; i < 16; ++i) {
        int e = tid + i * 256;
        sm_idx[e] = (unsigned char)rpe_idx[e];
    }

    const float4* xs4 = reinterpret_cast<const float4*>(sm_x);

    // =========================== per-head loop ===========================
    for (int h = 0; h < NHEAD; ++h) {
        // ---- GEMM1: qkv_h[64,96] = x[64,256] @ Wh[96,256]^T ----
        float acc1[4][6];
        #pragma unroll
        for (int i = 0; i < 4; ++i)
            #pragma unroll
            for (int j = 0; j < 6; ++j) acc1[i][j] = 0.f;

        const int d0 = lg * 6;  // 16 groups * 6 = 96 cols
        for (int kt = 0; kt < 8; ++kt) {
            __syncthreads();
            // load W tile [96 rows][32 K], padded rows of 33
            #pragma unroll
            for (int i = 0; i < 12; ++i) {
                int e  = tid + i * 256;
                int r  = e >> 5, kk = e & 31;
                int grp  = r >> 5;                       // 0=q,1=k,2=v
                int wrow = grp * 256 + h * 32 + (r & 31);
                sm_wt[r * WT_LD + kk] = Wqkv[wrow * 256 + kt * 32 + kk];
            }
            __syncthreads();
            #pragma unroll
            for (int k4 = 0; k4 < 8; ++k4) {
                float4 xv[4];
                #pragma unroll
                for (int i = 0; i < 4; ++i)
                    xv[i] = xs4[(t0 + i) * 64 + kt * 8 + k4];
                const float* xf = reinterpret_cast<const float*>(xv);
                #pragma unroll
                for (int kk = 0; kk < 4; ++kk) {
                    float w[6];
                    #pragma unroll
                    for (int j = 0; j < 6; ++j)
                        w[j] = sm_wt[(d0 + j) * WT_LD + k4 * 4 + kk];
                    #pragma unroll
                    for (int i = 0; i < 4; ++i) {
                        float xs = xf[i * 4 + kk];
                        #pragma unroll
                        for (int j = 0; j < 6; ++j)
                            acc1[i][j] += xs * w[j];
                    }
                }
            }
        }
        // scatter q / k / v^T to SMEM
        #pragma unroll
        for (int i = 0; i < 4; ++i) {
            int t = t0 + i;
            #pragma unroll
            for (int j = 0; j < 6; ++j) {
                int c = d0 + j;
                float v = acc1[i][j];
                if (c < 32)       sm_q[t * QK_LD + c]            = v;
                else if (c < 64)  sm_k[t * QK_LD + (c - 32)]     = v;
                else              sm_vt[(c - 64) * VT_LD + t]    = v;
            }
        }
        __syncthreads();

        // ---- GEMM2: s[64,64] = q @ k^T (raw scores) ----
        {
            float acc2[4][4];
            #pragma unroll
            for (int i = 0; i < 4; ++i)
                #pragma unroll
                for (int j = 0; j < 4; ++j) acc2[i][j] = 0.f;
            const float4* q4 = reinterpret_cast<const float4*>(sm_q);
            const float4* k4 = reinterpret_cast<const float4*>(sm_k);
            #pragma unroll
            for (int kk4 = 0; kk4 < 8; ++kk4) {
                float4 qv[4], kv[4];
                #pragma unroll
                for (int i = 0; i < 4; ++i) qv[i] = q4[(t0 + i) * 9 + kk4];
                #pragma unroll
                for (int j = 0; j < 4; ++j) kv[j] = k4[(lg + j * 16) * 9 + kk4];
                const float* qf = reinterpret_cast<const float*>(qv);
                const float* kf = reinterpret_cast<const float*>(kv);
                #pragma unroll
                for (int kk = 0; kk < 4; ++kk)
                    #pragma unroll
                    for (int i = 0; i < 4; ++i)
                        #pragma unroll
                        for (int j = 0; j < 4; ++j)
                            acc2[i][j] += qf[i * 4 + kk] * kf[j * 4 + kk];
            }
            #pragma unroll
            for (int i = 0; i < 4; ++i)
                #pragma unroll
                for (int j = 0; j < 4; ++j)
                    sm_s[(t0 + i) * S_LD + lg + j * 16] = acc2[i][j];
        }
        __syncthreads();

        // ---- softmax over rows: p = exp(s*scale + bias - max); rinv = 1/sum ----
        {
            int row = tid >> 2;
            int qq  = tid & 3;
            int cb  = qq * 16;
            float vals[16];
            float mx = -1e30f;
            #pragma unroll
            for (int c = 0; c < 16; ++c) {
                int col = cb + c;
                float sc = sm_s[row * S_LD + col] * SCALE
                         + sm_rpe[(int)sm_idx[row * 64 + col] * 8 + h];
                vals[c] = sc;
                mx = fmaxf(mx, sc);
            }
            mx = fmaxf(mx, __shfl_xor_sync(0xFFFFFFFFu, mx, 1));
            mx = fmaxf(mx, __shfl_xor_sync(0xFFFFFFFFu, mx, 2));
            float sum = 0.f;
            #pragma unroll
            for (int c = 0; c < 16; ++c) {
                float e = __expf(vals[c] - mx);
                sm_s[row * S_LD + cb + c] = e;
                sum += e;
            }
            sum += __shfl_xor_sync(0xFFFFFFFFu, sum, 1);
            sum += __shfl_xor_sync(0xFFFFFFFFu, sum, 2);
            if (qq == 0) sm_rinv[row] = 1.f / sum;
        }
        __syncthreads();

        // ---- GEMM3: out_h[64,32] = p @ v  (v stored transposed) ----
        {
            float acc3[4][2];
            #pragma unroll
            for (int i = 0; i < 4; ++i) { acc3[i][0] = 0.f; acc3[i][1] = 0.f; }
            const float4* s4 = reinterpret_cast<const float4*>(sm_s);
            const float4* v4 = reinterpret_cast<const float4*>(sm_vt);
            #pragma unroll
            for (int m4 = 0; m4 < 16; ++m4) {
                float4 pv[4], vv[2];
                #pragma unroll
                for (int i = 0; i < 4; ++i) pv[i] = s4[(t0 + i) * 17 + m4];
                #pragma unroll
                for (int j = 0; j < 2; ++j) vv[j] = v4[(lg + j * 16) * 17 + m4];
                const float* pf = reinterpret_cast<const float*>(pv);
                const float* vf = reinterpret_cast<const float*>(vv);
                #pragma unroll
                for (int kk = 0; kk < 4; ++kk)
                    #pragma unroll
                    for (int i = 0; i < 4; ++i)
                        #pragma unroll
                        for (int j = 0; j < 2; ++j)
                            acc3[i][j] += pf[i * 4 + kk] * vf[j * 4 + kk];
            }
            #pragma unroll
            for (int i = 0; i < 4; ++i) {
                float rv = sm_rinv[t0 + i];
                #pragma unroll
                for (int j = 0; j < 2; ++j)
                    sm_op[(t0 + i) * OP_LD + h * 32 + lg + j * 16] = acc3[i][j] * rv;
            }
        }
        // next-head hazards covered by the sync at top of the GEMM1 kt-loop
    }

    // =========================== GEMM4: y = out_pre @ Wproj^T ===========================
    {
        const float4* op4 = reinterpret_cast<const float4*>(sm_op);  // row = 65 float4
        float* yg = y + (size_t)win * (64 * 256);
        for (int half = 0; half < 2; ++half) {
            float acc4[4][8];
            #pragma unroll
            for (int i = 0; i < 4; ++i)
                #pragma unroll
                for (int j = 0; j < 8; ++j) acc4[i][j] = 0.f;

            for (int kt = 0; kt < 8; ++kt) {
                __syncthreads();
                // load Wproj tile [128 rows][32], padded rows of 33
                #pragma unroll
                for (int i = 0; i < 16; ++i) {
                    int e = tid + i * 256;
                    int r = e >> 5, kk = e & 31;
                    sm_wt[r * WT_LD + kk] =
                        Wproj[(half * 128 + r) * 256 + kt * 32 + kk];
                }
                __syncthreads();
                #pragma unroll
                for (int k4 = 0; k4 < 8; ++k4) {
                    float4 ov[4];
                    #pragma unroll
                    for (int i = 0; i < 4; ++i)
                        ov[i] = op4[(t0 + i) * 65 + kt * 8 + k4];
                    const float* of = reinterpret_cast<const float*>(ov);
                    #pragma unroll
                    for (int kk = 0; kk < 4; ++kk) {
                        float w[8];
                        #pragma unroll
                        for (int j = 0; j < 8; ++j)
                            w[j] = sm_wt[(lg + j * 16) * WT_LD + k4 * 4 + kk];
                        #pragma unroll
                        for (int i = 0; i < 4; ++i) {
                            float ox = of[i * 4 + kk];
                            #pragma unroll
                            for (int j = 0; j < 8; ++j)
                                acc4[i][j] += ox * w[j];
                        }
                    }
                }
            }
            #pragma unroll
            for (int i = 0; i < 4; ++i)
                #pragma unroll
                for (int j = 0; j < 8; ++j)
                    yg[(t0 + i) * 256 + half * 128 + lg + j * 16] = acc4[i][j];
        }
    }
}

extern "C" void kernel_launch(void* const* d_in, const int* in_sizes, int n_in,
                              void* d_out, int out_size)
{
    const float* x     = (const float*)d_in[0];
    const float* Wqkv  = (const float*)d_in[1];
    const float* Wproj = (const float*)d_in[2];
    const float* rpe   = (const float*)d_in[3];
    const int*   ridx  = (const int*)d_in[4];
    float* y = (float*)d_out;

    cudaFuncSetAttribute(wmsa_fused_kernel,
                         cudaFuncAttributeMaxDynamicSharedMemorySize, SMEM_BYTES);
    wmsa_fused_kernel<<<4096, 256, SMEM_BYTES>>>(x, Wqkv, Wproj, rpe, ridx, y);
}

// round 8
// speedup vs baseline: 1.0010x; 1.0010x over previous
#include <cuda_runtime.h>

// WindowMSA fused kernel: one CTA per window (4096 windows).
// Per window: qkv = x @ Wqkv^T (per head), attn = softmax(qk^T*scale + bias),
// out_h = attn @ v, y = out @ Wproj^T. Everything staged in SMEM, fp32 FFMA.

#define NTOK 64
#define CDIM 256
#define NHEAD 8
#define HDIM 32
#define SCALE 0.17677669529663687f   // 1/sqrt(32)

// ---- shared memory layout (in floats) ----
#define OFF_X    0
#define SZ_X     (64*256)            // x tile, row-major [64][256]
#define OFF_OP   (OFF_X + SZ_X)      // pre-proj output [64][260] (pad 4)
#define OP_LD    260
#define SZ_OP    (64*OP_LD)
#define OFF_Q    (OFF_OP + SZ_OP)    // q [64][36]
#define QK_LD    36
#define SZ_Q     (64*QK_LD)
#define OFF_K    (OFF_Q + SZ_Q)      // k [64][36]
#define SZ_K     (64*QK_LD)
#define OFF_VT   (OFF_K + SZ_K)      // v transposed [32][68]
#define VT_LD    68
#define SZ_VT    (32*VT_LD)
#define OFF_S    (OFF_VT + SZ_VT)    // scores / probs [64][68]
#define S_LD     68
#define SZ_S     (64*S_LD)
#define OFF_WT   (OFF_S + SZ_S)      // weight K-tile, up to [128][33]
#define WT_LD    33
#define SZ_WT    (128*WT_LD)
#define OFF_RPE  (OFF_WT + SZ_WT)    // rpe table [225*8]
#define SZ_RPE   (225*8)
#define OFF_RINV (OFF_RPE + SZ_RPE)  // 1/rowsum [64]
#define SZ_RINV  64
#define OFF_IDX  (OFF_RINV + SZ_RINV) // rpe_idx as uchar[4096] = 1024 floats
#define SZ_IDX_F 1024
#define SMEM_FLOATS (OFF_IDX + SZ_IDX_F)
#define SMEM_BYTES  (SMEM_FLOATS * 4)   // 205,088 B

__global__ void __launch_bounds__(256, 1)
wmsa_fused_kernel(const float* __restrict__ x,
                  const float* __restrict__ Wqkv,
                  const float* __restrict__ Wproj,
                  const float* __restrict__ rpe,
                  const int*   __restrict__ rpe_idx,
                  float*       __restrict__ y)
{
    extern __shared__ float sm[];
    float* sm_x    = sm + OFF_X;
    float* sm_op   = sm + OFF_OP;
    float* sm_q    = sm + OFF_Q;
    float* sm_k    = sm + OFF_K;
    float* sm_vt   = sm + OFF_VT;
    float* sm_s    = sm + OFF_S;
    float* sm_wt   = sm + OFF_WT;
    float* sm_rpe  = sm + OFF_RPE;
    float* sm_rinv = sm + OFF_RINV;
    unsigned char* sm_idx = (unsigned char*)(sm + OFF_IDX);

    const int tid = threadIdx.x;
    const int win = blockIdx.x;
    const int tg  = tid >> 4;   // 0..15 -> token group (4 rows)
    const int lg  = tid & 15;   // 0..15 -> column group
    const int t0  = tg * 4;

    // ---- stage x (float4, coalesced) ----
    {
        const float4* xg = reinterpret_cast<const float4*>(x + (size_t)win * (64 * 256));
        float4* xs4 = reinterpret_cast<float4*>(sm_x);
        #pragma unroll
        for (int i = 0; i < 16; ++i)
            xs4[tid + i * 256] = xg[tid + i * 256];
    }
    // ---- stage rpe table + rpe_idx (as uint8; values < 225) ----
    for (int i = tid; i < 225 * 8; i += 256)
        sm_rpe[i] = rpe[i];
    #pragma unroll
    for (int i = 0; i < 16; ++i) {
        int e = tid + i * 256;
        sm_idx[e] = (unsigned char)rpe_idx[e];
    }

    const float4* xs4 = reinterpret_cast<const float4*>(sm_x);

    // =========================== per-head loop ===========================
    for (int h = 0; h < NHEAD; ++h) {
        // ---- GEMM1: qkv_h[64,96] = x[64,256] @ Wh[96,256]^T ----
        float acc1[4][6];
        #pragma unroll
        for (int i = 0; i < 4; ++i)
            #pragma unroll
            for (int j = 0; j < 6; ++j) acc1[i][j] = 0.f;

        const int d0 = lg * 6;  // 16 groups * 6 = 96 cols
        for (int kt = 0; kt < 8; ++kt) {
            __syncthreads();
            // load W tile [96 rows][32 K], padded rows of 33
            #pragma unroll
            for (int i = 0; i < 12; ++i) {
                int e  = tid + i * 256;
                int r  = e >> 5, kk = e & 31;
                int grp  = r >> 5;                       // 0=q,1=k,2=v
                int wrow = grp * 256 + h * 32 + (r & 31);
                sm_wt[r * WT_LD + kk] = Wqkv[wrow * 256 + kt * 32 + kk];
            }
            __syncthreads();
            #pragma unroll
            for (int k4 = 0; k4 < 8; ++k4) {
                float4 xv[4];
                #pragma unroll
                for (int i = 0; i < 4; ++i)
                    xv[i] = xs4[(t0 + i) * 64 + kt * 8 + k4];
                const float* xf = reinterpret_cast<const float*>(xv);
                #pragma unroll
                for (int kk = 0; kk < 4; ++kk) {
                    float w[6];
                    #pragma unroll
                    for (int j = 0; j < 6; ++j)
                        w[j] = sm_wt[(d0 + j) * WT_LD + k4 * 4 + kk];
                    #pragma unroll
                    for (int i = 0; i < 4; ++i) {
                        float xs = xf[i * 4 + kk];
                        #pragma unroll
                        for (int j = 0; j < 6; ++j)
                            acc1[i][j] += xs * w[j];
                    }
                }
            }
        }
        // scatter q / k / v^T to SMEM
        #pragma unroll
        for (int i = 0; i < 4; ++i) {
            int t = t0 + i;
            #pragma unroll
            for (int j = 0; j < 6; ++j) {
                int c = d0 + j;
                float v = acc1[i][j];
                if (c < 32)       sm_q[t * QK_LD + c]            = v;
                else if (c < 64)  sm_k[t * QK_LD + (c - 32)]     = v;
                else              sm_vt[(c - 64) * VT_LD + t]    = v;
            }
        }
        __syncthreads();

        // ---- GEMM2: s[64,64] = q @ k^T (raw scores) ----
        {
            float acc2[4][4];
            #pragma unroll
            for (int i = 0; i < 4; ++i)
                #pragma unroll
                for (int j = 0; j < 4; ++j) acc2[i][j] = 0.f;
            const float4* q4 = reinterpret_cast<const float4*>(sm_q);
            const float4* k4 = reinterpret_cast<const float4*>(sm_k);
            #pragma unroll
            for (int kk4 = 0; kk4 < 8; ++kk4) {
                float4 qv[4], kv[4];
                #pragma unroll
                for (int i = 0; i < 4; ++i) qv[i] = q4[(t0 + i) * 9 + kk4];
                #pragma unroll
                for (int j = 0; j < 4; ++j) kv[j] = k4[(lg + j * 16) * 9 + kk4];
                const float* qf = reinterpret_cast<const float*>(qv);
                const float* kf = reinterpret_cast<const float*>(kv);
                #pragma unroll
                for (int kk = 0; kk < 4; ++kk)
                    #pragma unroll
                    for (int i = 0; i < 4; ++i)
                        #pragma unroll
                        for (int j = 0; j < 4; ++j)
                            acc2[i][j] += qf[i * 4 + kk] * kf[j * 4 + kk];
            }
            #pragma unroll
            for (int i = 0; i < 4; ++i)
                #pragma unroll
                for (int j = 0; j < 4; ++j)
                    sm_s[(t0 + i) * S_LD + lg + j * 16] = acc2[i][j];
        }
        __syncthreads();

        // ---- softmax over rows: p = exp(s*scale + bias - max); rinv = 1/sum ----
        {
            int row = tid >> 2;
            int qq  = tid & 3;
            int cb  = qq * 16;
            float vals[16];
            float mx = -1e30f;
            #pragma unroll
            for (int c = 0; c < 16; ++c) {
                int col = cb + c;
                float sc = sm_s[row * S_LD + col] * SCALE
                         + sm_rpe[(int)sm_idx[row * 64 + col] * 8 + h];
                vals[c] = sc;
                mx = fmaxf(mx, sc);
            }
            mx = fmaxf(mx, __shfl_xor_sync(0xFFFFFFFFu, mx, 1));
            mx = fmaxf(mx, __shfl_xor_sync(0xFFFFFFFFu, mx, 2));
            float sum = 0.f;
            #pragma unroll
            for (int c = 0; c < 16; ++c) {
                float e = __expf(vals[c] - mx);
                sm_s[row * S_LD + cb + c] = e;
                sum += e;
            }
            sum += __shfl_xor_sync(0xFFFFFFFFu, sum, 1);
            sum += __shfl_xor_sync(0xFFFFFFFFu, sum, 2);
            if (qq == 0) sm_rinv[row] = 1.f / sum;
        }
        __syncthreads();

        // ---- GEMM3: out_h[64,32] = p @ v  (v stored transposed) ----
        {
            float acc3[4][2];
            #pragma unroll
            for (int i = 0; i < 4; ++i) { acc3[i][0] = 0.f; acc3[i][1] = 0.f; }
            const float4* s4 = reinterpret_cast<const float4*>(sm_s);
            const float4* v4 = reinterpret_cast<const float4*>(sm_vt);
            #pragma unroll
            for (int m4 = 0; m4 < 16; ++m4) {
                float4 pv[4], vv[2];
                #pragma unroll
                for (int i = 0; i < 4; ++i) pv[i] = s4[(t0 + i) * 17 + m4];
                #pragma unroll
                for (int j = 0; j < 2; ++j) vv[j] = v4[(lg + j * 16) * 17 + m4];
                const float* pf = reinterpret_cast<const float*>(pv);
                const float* vf = reinterpret_cast<const float*>(vv);
                #pragma unroll
                for (int kk = 0; kk < 4; ++kk)
                    #pragma unroll
                    for (int i = 0; i < 4; ++i)
                        #pragma unroll
                        for (int j = 0; j < 2; ++j)
                            acc3[i][j] += pf[i * 4 + kk] * vf[j * 4 + kk];
            }
            #pragma unroll
            for (int i = 0; i < 4; ++i) {
                float rv = sm_rinv[t0 + i];
                #pragma unroll
                for (int j = 0; j < 2; ++j)
                    sm_op[(t0 + i) * OP_LD + h * 32 + lg + j * 16] = acc3[i][j] * rv;
            }
        }
        // next-head hazards covered by the sync at top of the GEMM1 kt-loop
    }

    // =========================== GEMM4: y = out_pre @ Wproj^T ===========================
    {
        const float4* op4 = reinterpret_cast<const float4*>(sm_op);  // row = 65 float4
        float* yg = y + (size_t)win * (64 * 256);
        for (int half = 0; half < 2; ++half) {
            float acc4[4][8];
            #pragma unroll
            for (int i = 0; i < 4; ++i)
                #pragma unroll
                for (int j = 0; j < 8; ++j) acc4[i][j] = 0.f;

            for (int kt = 0; kt < 8; ++kt) {
                __syncthreads();
                // load Wproj tile [128 rows][32], padded rows of 33
                #pragma unroll
                for (int i = 0; i < 16; ++i) {
                    int e = tid + i * 256;
                    int r = e >> 5, kk = e & 31;
                    sm_wt[r * WT_LD + kk] =
                        Wproj[(half * 128 + r) * 256 + kt * 32 + kk];
                }
                __syncthreads();
                #pragma unroll
                for (int k4 = 0; k4 < 8; ++k4) {
                    float4 ov[4];
                    #pragma unroll
                    for (int i = 0; i < 4; ++i)
                        ov[i] = op4[(t0 + i) * 65 + kt * 8 + k4];
                    const float* of = reinterpret_cast<const float*>(ov);
                    #pragma unroll
                    for (int kk = 0; kk < 4; ++kk) {
                        float w[8];
                        #pragma unroll
                        for (int j = 0; j < 8; ++j)
                            w[j] = sm_wt[(lg + j * 16) * WT_LD + k4 * 4 + kk];
                        #pragma unroll
                        for (int i = 0; i < 4; ++i) {
                            float ox = of[i * 4 + kk];
                            #pragma unroll
                            for (int j = 0; j < 8; ++j)
                                acc4[i][j] += ox * w[j];
                        }
                    }
                }
            }
            #pragma unroll
            for (int i = 0; i < 4; ++i)
                #pragma unroll
                for (int j = 0; j < 8; ++j)
                    yg[(t0 + i) * 256 + half * 128 + lg + j * 16] = acc4[i][j];
        }
    }
}

extern "C" void kernel_launch(void* const* d_in, const int* in_sizes, int n_in,
                              void* d_out, int out_size)
{
    const float* x     = (const float*)d_in[0];
    const float* Wqkv  = (const float*)d_in[1];
    const float* Wproj = (const float*)d_in[2];
    const float* rpe   = (const float*)d_in[3];
    const int*   ridx  = (const int*)d_in[4];
    float* y = (float*)d_out;

    cudaFuncSetAttribute(wmsa_fused_kernel,
                         cudaFuncAttributeMaxDynamicSharedMemorySize, SMEM_BYTES);
    wmsa_fused_kernel<<<4096, 256, SMEM_BYTES>>>(x, Wqkv, Wproj, rpe, ridx, y);
}

// round 9
// speedup vs baseline: 1.0276x; 1.0265x over previous
#include <cuda_runtime.h>

// WindowMSA fused kernel: one CTA per window (4096 windows).
// GEMM1/GEMM4 use packed fma.rn.f32x2 (2 fp32 FMA per issue slot) with
// transposed weight tiles in SMEM. Attention core unchanged (fp32 FFMA).

#define NTOK 64
#define CDIM 256
#define NHEAD 8
#define HDIM 32
#define SCALE 0.17677669529663687f   // 1/sqrt(32)

// ---- shared memory layout (in floats) ----
#define OFF_X    0
#define SZ_X     (64*256)            // x tile, row-major [64][256]
#define OFF_OP   (OFF_X + SZ_X)      // pre-proj output [64][260] (pad 4)
#define OP_LD    260
#define SZ_OP    (64*OP_LD)
#define OFF_Q    (OFF_OP + SZ_OP)    // q [64][36]
#define QK_LD    36
#define SZ_Q     (64*QK_LD)
#define OFF_K    (OFF_Q + SZ_Q)      // k [64][36]
#define SZ_K     (64*QK_LD)
#define OFF_VT   (OFF_K + SZ_K)      // v transposed [32][68]
#define VT_LD    68
#define SZ_VT    (32*VT_LD)
#define OFF_S    (OFF_VT + SZ_VT)    // scores / probs [64][68]
#define S_LD     68
#define SZ_S     (64*S_LD)
#define OFF_WT   (OFF_S + SZ_S)      // transposed weight K-tile (max 32x130)
#define W1_LD    98                  // GEMM1: [32 k][96 d] pad->98 (even)
#define W4_LD    130                 // GEMM4: [32 k][128 d] pad->130 (even)
#define SZ_WT    (32*W4_LD)          // 4160 floats
#define OFF_RPE  (OFF_WT + SZ_WT)    // rpe table [225*8]
#define SZ_RPE   (225*8)
#define OFF_RINV (OFF_RPE + SZ_RPE)  // 1/rowsum [64]
#define SZ_RINV  64
#define OFF_IDX  (OFF_RINV + SZ_RINV) // rpe_idx as uchar[4096] = 1024 floats
#define SZ_IDX_F 1024
#define SMEM_FLOATS (OFF_IDX + SZ_IDX_F)
#define SMEM_BYTES  (SMEM_FLOATS * 4)

typedef unsigned long long u64;

__device__ __forceinline__ float lo32(u64 v) {
    return __uint_as_float((unsigned)(v & 0xffffffffu));
}
__device__ __forceinline__ float hi32(u64 v) {
    return __uint_as_float((unsigned)(v >> 32));
}
__device__ __forceinline__ u64 bcast2(float x) {
    u64 r;
    asm("mov.b64 %0, {%1, %1};" : "=l"(r) : "r"(__float_as_uint(x)));
    return r;
}
__device__ __forceinline__ void fma2(u64& acc, u64 a, u64 b) {
    asm("fma.rn.f32x2 %0, %1, %2, %0;" : "+l"(acc) : "l"(a), "l"(b));
}

__global__ void __launch_bounds__(256, 1)
wmsa_fused_kernel(const float* __restrict__ x,
                  const float* __restrict__ Wqkv,
                  const float* __restrict__ Wproj,
                  const float* __restrict__ rpe,
                  const int*   __restrict__ rpe_idx,
                  float*       __restrict__ y)
{
    extern __shared__ float sm[];
    float* sm_x    = sm + OFF_X;
    float* sm_op   = sm + OFF_OP;
    float* sm_q    = sm + OFF_Q;
    float* sm_k    = sm + OFF_K;
    float* sm_vt   = sm + OFF_VT;
    float* sm_s    = sm + OFF_S;
    float* sm_wt   = sm + OFF_WT;
    float* sm_rpe  = sm + OFF_RPE;
    float* sm_rinv = sm + OFF_RINV;
    unsigned char* sm_idx = (unsigned char*)(sm + OFF_IDX);

    const int tid = threadIdx.x;
    const int win = blockIdx.x;
    const int tg  = tid >> 4;   // 0..15 -> token group (4 rows)
    const int lg  = tid & 15;   // 0..15 -> column group
    const int t0  = tg * 4;

    // ---- stage x (float4, coalesced) ----
    {
        const float4* xg = reinterpret_cast<const float4*>(x + (size_t)win * (64 * 256));
        float4* xs4w = reinterpret_cast<float4*>(sm_x);
        #pragma unroll
        for (int i = 0; i < 16; ++i)
            xs4w[tid + i * 256] = xg[tid + i * 256];
    }
    // ---- stage rpe table + rpe_idx (as uint8; values < 225) ----
    for (int i = tid; i < 225 * 8; i += 256)
        sm_rpe[i] = rpe[i];
    #pragma unroll
    for (int i = 0; i < 16; ++i) {
        int e = tid + i * 256;
        sm_idx[e] = (unsigned char)rpe_idx[e];
    }

    const float4* xs4 = reinterpret_cast<const float4*>(sm_x);

    // =========================== per-head loop ===========================
    for (int h = 0; h < NHEAD; ++h) {
        // ---- GEMM1: qkv_h[64,96] = x[64,256] @ Wh[96,256]^T, f32x2 packed ----
        const int d0 = lg * 6;          // 16 groups * 6 = 96 cols, pairs at d0+2p
        u64 acc1[4][3];
        #pragma unroll
        for (int i = 0; i < 4; ++i)
            #pragma unroll
            for (int p = 0; p < 3; ++p) acc1[i][p] = 0ull;

        for (int kt = 0; kt < 8; ++kt) {
            __syncthreads();
            // stage transposed W tile: wt[kk][r], r in [0,96), kk in [0,32)
            #pragma unroll
            for (int i = 0; i < 12; ++i) {
                int e  = tid + i * 256;
                int r  = e >> 5, kk = e & 31;          // coalesced over kk
                int grp  = r >> 5;                     // 0=q,1=k,2=v
                int wrow = grp * 256 + h * 32 + (r & 31);
                sm_wt[kk * W1_LD + r] = Wqkv[wrow * 256 + kt * 32 + kk];
            }
            __syncthreads();
            #pragma unroll
            for (int k4 = 0; k4 < 8; ++k4) {
                float4 xv[4];
                #pragma unroll
                for (int i = 0; i < 4; ++i)
                    xv[i] = xs4[(t0 + i) * 64 + kt * 8 + k4];
                const float* xf = reinterpret_cast<const float*>(xv);
                #pragma unroll
                for (int kk = 0; kk < 4; ++kk) {
                    const float* wr = sm_wt + (k4 * 4 + kk) * W1_LD + d0;
                    u64 w0 = *reinterpret_cast<const u64*>(wr);
                    u64 w1 = *reinterpret_cast<const u64*>(wr + 2);
                    u64 w2 = *reinterpret_cast<const u64*>(wr + 4);
                    #pragma unroll
                    for (int i = 0; i < 4; ++i) {
                        u64 xx = bcast2(xf[i * 4 + kk]);
                        fma2(acc1[i][0], xx, w0);
                        fma2(acc1[i][1], xx, w1);
                        fma2(acc1[i][2], xx, w2);
                    }
                }
            }
        }
        // scatter q / k / v^T to SMEM
        #pragma unroll
        for (int i = 0; i < 4; ++i) {
            int t = t0 + i;
            #pragma unroll
            for (int p = 0; p < 3; ++p) {
                float v0 = lo32(acc1[i][p]);
                float v1 = hi32(acc1[i][p]);
                #pragma unroll
                for (int s = 0; s < 2; ++s) {
                    int c = d0 + 2 * p + s;
                    float v = s ? v1 : v0;
                    if (c < 32)       sm_q[t * QK_LD + c]         = v;
                    else if (c < 64)  sm_k[t * QK_LD + (c - 32)]  = v;
                    else              sm_vt[(c - 64) * VT_LD + t] = v;
                }
            }
        }
        __syncthreads();

        // ---- GEMM2: s[64,64] = q @ k^T (raw scores) ----
        {
            float acc2[4][4];
            #pragma unroll
            for (int i = 0; i < 4; ++i)
                #pragma unroll
                for (int j = 0; j < 4; ++j) acc2[i][j] = 0.f;
            const float4* q4 = reinterpret_cast<const float4*>(sm_q);
            const float4* k4 = reinterpret_cast<const float4*>(sm_k);
            #pragma unroll
            for (int kk4 = 0; kk4 < 8; ++kk4) {
                float4 qv[4], kv[4];
                #pragma unroll
                for (int i = 0; i < 4; ++i) qv[i] = q4[(t0 + i) * 9 + kk4];
                #pragma unroll
                for (int j = 0; j < 4; ++j) kv[j] = k4[(lg + j * 16) * 9 + kk4];
                const float* qf = reinterpret_cast<const float*>(qv);
                const float* kf = reinterpret_cast<const float*>(kv);
                #pragma unroll
                for (int kk = 0; kk < 4; ++kk)
                    #pragma unroll
                    for (int i = 0; i < 4; ++i)
                        #pragma unroll
                        for (int j = 0; j < 4; ++j)
                            acc2[i][j] += qf[i * 4 + kk] * kf[j * 4 + kk];
            }
            #pragma unroll
            for (int i = 0; i < 4; ++i)
                #pragma unroll
                for (int j = 0; j < 4; ++j)
                    sm_s[(t0 + i) * S_LD + lg + j * 16] = acc2[i][j];
        }
        __syncthreads();

        // ---- softmax over rows: p = exp(s*scale + bias - max); rinv = 1/sum ----
        {
            int row = tid >> 2;
            int qq  = tid & 3;
            int cb  = qq * 16;
            float vals[16];
            float mx = -1e30f;
            #pragma unroll
            for (int c = 0; c < 16; ++c) {
                int col = cb + c;
                float sc = sm_s[row * S_LD + col] * SCALE
                         + sm_rpe[(int)sm_idx[row * 64 + col] * 8 + h];
                vals[c] = sc;
                mx = fmaxf(mx, sc);
            }
            mx = fmaxf(mx, __shfl_xor_sync(0xFFFFFFFFu, mx, 1));
            mx = fmaxf(mx, __shfl_xor_sync(0xFFFFFFFFu, mx, 2));
            float sum = 0.f;
            #pragma unroll
            for (int c = 0; c < 16; ++c) {
                float e = __expf(vals[c] - mx);
                sm_s[row * S_LD + cb + c] = e;
                sum += e;
            }
            sum += __shfl_xor_sync(0xFFFFFFFFu, sum, 1);
            sum += __shfl_xor_sync(0xFFFFFFFFu, sum, 2);
            if (qq == 0) sm_rinv[row] = 1.f / sum;
        }
        __syncthreads();

        // ---- GEMM3: out_h[64,32] = p @ v  (v stored transposed) ----
        {
            float acc3[4][2];
            #pragma unroll
            for (int i = 0; i < 4; ++i) { acc3[i][0] = 0.f; acc3[i][1] = 0.f; }
            const float4* s4 = reinterpret_cast<const float4*>(sm_s);
            const float4* v4 = reinterpret_cast<const float4*>(sm_vt);
            #pragma unroll
            for (int m4 = 0; m4 < 16; ++m4) {
                float4 pv[4], vv[2];
                #pragma unroll
                for (int i = 0; i < 4; ++i) pv[i] = s4[(t0 + i) * 17 + m4];
                #pragma unroll
                for (int j = 0; j < 2; ++j) vv[j] = v4[(lg + j * 16) * 17 + m4];
                const float* pf = reinterpret_cast<const float*>(pv);
                const float* vf = reinterpret_cast<const float*>(vv);
                #pragma unroll
                for (int kk = 0; kk < 4; ++kk)
                    #pragma unroll
                    for (int i = 0; i < 4; ++i)
                        #pragma unroll
                        for (int j = 0; j < 2; ++j)
                            acc3[i][j] += pf[i * 4 + kk] * vf[j * 4 + kk];
            }
            #pragma unroll
            for (int i = 0; i < 4; ++i) {
                float rv = sm_rinv[t0 + i];
                #pragma unroll
                for (int j = 0; j < 2; ++j)
                    sm_op[(t0 + i) * OP_LD + h * 32 + lg + j * 16] = acc3[i][j] * rv;
            }
        }
        // next-head hazards covered by the sync at top of the GEMM1 kt-loop
    }

    // ================ GEMM4: y = out_pre @ Wproj^T, f32x2 packed ================
    {
        const float4* op4 = reinterpret_cast<const float4*>(sm_op);  // row = 65 float4
        float* yg = y + (size_t)win * (64 * 256);
        for (int half = 0; half < 2; ++half) {
            u64 acc4[4][4];
            #pragma unroll
            for (int i = 0; i < 4; ++i)
                #pragma unroll
                for (int p = 0; p < 4; ++p) acc4[i][p] = 0ull;

            for (int kt = 0; kt < 8; ++kt) {
                __syncthreads();
                // stage transposed Wproj tile: wt[kk][r], r in [0,128)
                #pragma unroll
                for (int i = 0; i < 16; ++i) {
                    int e = tid + i * 256;
                    int r = e >> 5, kk = e & 31;       // coalesced over kk
                    sm_wt[kk * W4_LD + r] =
                        Wproj[(half * 128 + r) * 256 + kt * 32 + kk];
                }
                __syncthreads();
                #pragma unroll
                for (int k4 = 0; k4 < 8; ++k4) {
                    float4 ov[4];
                    #pragma unroll
                    for (int i = 0; i < 4; ++i)
                        ov[i] = op4[(t0 + i) * 65 + kt * 8 + k4];
                    const float* of = reinterpret_cast<const float*>(ov);
                    #pragma unroll
                    for (int kk = 0; kk < 4; ++kk) {
                        const float* wr = sm_wt + (k4 * 4 + kk) * W4_LD + lg * 2;
                        u64 w[4];
                        #pragma unroll
                        for (int p = 0; p < 4; ++p)
                            w[p] = *reinterpret_cast<const u64*>(wr + p * 32);
                        #pragma unroll
                        for (int i = 0; i < 4; ++i) {
                            u64 xx = bcast2(of[i * 4 + kk]);
                            #pragma unroll
                            for (int p = 0; p < 4; ++p)
                                fma2(acc4[i][p], xx, w[p]);
                        }
                    }
                }
            }
            // cols = half*128 + p*32 + lg*2 (+1): coalesced float2 stores
            #pragma unroll
            for (int i = 0; i < 4; ++i)
                #pragma unroll
                for (int p = 0; p < 4; ++p) {
                    float2 v2 = make_float2(lo32(acc4[i][p]), hi32(acc4[i][p]));
                    *reinterpret_cast<float2*>(
                        yg + (t0 + i) * 256 + half * 128 + p * 32 + lg * 2) = v2;
                }
        }
    }
}

extern "C" void kernel_launch(void* const* d_in, const int* in_sizes, int n_in,
                              void* d_out, int out_size)
{
    const float* x     = (const float*)d_in[0];
    const float* Wqkv  = (const float*)d_in[1];
    const float* Wproj = (const float*)d_in[2];
    const float* rpe   = (const float*)d_in[3];
    const int*   ridx  = (const int*)d_in[4];
    float* y = (float*)d_out;

    cudaFuncSetAttribute(wmsa_fused_kernel,
                         cudaFuncAttributeMaxDynamicSharedMemorySize, SMEM_BYTES);
    wmsa_fused_kernel<<<4096, 256, SMEM_BYTES>>>(x, Wqkv, Wproj, rpe, ridx, y);
}

// round 10
// speedup vs baseline: 1.0834x; 1.0543x over previous
#include <cuda_runtime.h>

// WindowMSA fused kernel: one CTA per window (4096 windows).
// GEMM1/GEMM4 use packed fma.rn.f32x2 (2 fp32 FMA per issue slot) with
// transposed weight tiles in SMEM. Attention core unchanged (fp32 FFMA).

#define NTOK 64
#define CDIM 256
#define NHEAD 8
#define HDIM 32
#define SCALE 0.17677669529663687f   // 1/sqrt(32)

// ---- shared memory layout (in floats) ----
#define OFF_X    0
#define SZ_X     (64*256)            // x tile, row-major [64][256]
#define OFF_OP   (OFF_X + SZ_X)      // pre-proj output [64][260] (pad 4)
#define OP_LD    260
#define SZ_OP    (64*OP_LD)
#define OFF_Q    (OFF_OP + SZ_OP)    // q [64][36]
#define QK_LD    36
#define SZ_Q     (64*QK_LD)
#define OFF_K    (OFF_Q + SZ_Q)      // k [64][36]
#define SZ_K     (64*QK_LD)
#define OFF_VT   (OFF_K + SZ_K)      // v transposed [32][68]
#define VT_LD    68
#define SZ_VT    (32*VT_LD)
#define OFF_S    (OFF_VT + SZ_VT)    // scores / probs [64][68]
#define S_LD     68
#define SZ_S     (64*S_LD)
#define OFF_WT   (OFF_S + SZ_S)      // transposed weight K-tile (max 32x130)
#define W1_LD    98                  // GEMM1: [32 k][96 d] pad->98 (even)
#define W4_LD    130                 // GEMM4: [32 k][128 d] pad->130 (even)
#define SZ_WT    (32*W4_LD)          // 4160 floats
#define OFF_RPE  (OFF_WT + SZ_WT)    // rpe table [225*8]
#define SZ_RPE   (225*8)
#define OFF_RINV (OFF_RPE + SZ_RPE)  // 1/rowsum [64]
#define SZ_RINV  64
#define OFF_IDX  (OFF_RINV + SZ_RINV) // rpe_idx as uchar[4096] = 1024 floats
#define SZ_IDX_F 1024
#define SMEM_FLOATS (OFF_IDX + SZ_IDX_F)
#define SMEM_BYTES  (SMEM_FLOATS * 4)

typedef unsigned long long u64;

__device__ __forceinline__ float lo32(u64 v) {
    return __uint_as_float((unsigned)(v & 0xffffffffu));
}
__device__ __forceinline__ float hi32(u64 v) {
    return __uint_as_float((unsigned)(v >> 32));
}
__device__ __forceinline__ u64 bcast2(float x) {
    u64 r;
    asm("mov.b64 %0, {%1, %1};" : "=l"(r) : "r"(__float_as_uint(x)));
    return r;
}
__device__ __forceinline__ void fma2(u64& acc, u64 a, u64 b) {
    asm("fma.rn.f32x2 %0, %1, %2, %0;" : "+l"(acc) : "l"(a), "l"(b));
}

__global__ void __launch_bounds__(256, 1)
wmsa_fused_kernel(const float* __restrict__ x,
                  const float* __restrict__ Wqkv,
                  const float* __restrict__ Wproj,
                  const float* __restrict__ rpe,
                  const int*   __restrict__ rpe_idx,
                  float*       __restrict__ y)
{
    extern __shared__ float sm[];
    float* sm_x    = sm + OFF_X;
    float* sm_op   = sm + OFF_OP;
    float* sm_q    = sm + OFF_Q;
    float* sm_k    = sm + OFF_K;
    float* sm_vt   = sm + OFF_VT;
    float* sm_s    = sm + OFF_S;
    float* sm_wt   = sm + OFF_WT;
    float* sm_rpe  = sm + OFF_RPE;
    float* sm_rinv = sm + OFF_RINV;
    unsigned char* sm_idx = (unsigned char*)(sm + OFF_IDX);

    const int tid = threadIdx.x;
    const int win = blockIdx.x;
    const int tg  = tid >> 4;   // 0..15 -> token group (4 rows)
    const int lg  = tid & 15;   // 0..15 -> column group
    const int t0  = tg * 4;

    // ---- stage x (float4, coalesced) ----
    {
        const float4* xg = reinterpret_cast<const float4*>(x + (size_t)win * (64 * 256));
        float4* xs4w = reinterpret_cast<float4*>(sm_x);
        #pragma unroll
        for (int i = 0; i < 16; ++i)
            xs4w[tid + i * 256] = xg[tid + i * 256];
    }
    // ---- stage rpe table + rpe_idx (as uint8; values < 225) ----
    for (int i = tid; i < 225 * 8; i += 256)
        sm_rpe[i] = rpe[i];
    #pragma unroll
    for (int i = 0; i < 16; ++i) {
        int e = tid + i * 256;
        sm_idx[e] = (unsigned char)rpe_idx[e];
    }

    const float4* xs4 = reinterpret_cast<const float4*>(sm_x);

    // =========================== per-head loop ===========================
    for (int h = 0; h < NHEAD; ++h) {
        // ---- GEMM1: qkv_h[64,96] = x[64,256] @ Wh[96,256]^T, f32x2 packed ----
        const int d0 = lg * 6;          // 16 groups * 6 = 96 cols, pairs at d0+2p
        u64 acc1[4][3];
        #pragma unroll
        for (int i = 0; i < 4; ++i)
            #pragma unroll
            for (int p = 0; p < 3; ++p) acc1[i][p] = 0ull;

        for (int kt = 0; kt < 8; ++kt) {
            __syncthreads();
            // stage transposed W tile: wt[kk][r], r in [0,96), kk in [0,32)
            #pragma unroll
            for (int i = 0; i < 12; ++i) {
                int e  = tid + i * 256;
                int r  = e >> 5, kk = e & 31;          // coalesced over kk
                int grp  = r >> 5;                     // 0=q,1=k,2=v
                int wrow = grp * 256 + h * 32 + (r & 31);
                sm_wt[kk * W1_LD + r] = Wqkv[wrow * 256 + kt * 32 + kk];
            }
            __syncthreads();
            #pragma unroll
            for (int k4 = 0; k4 < 8; ++k4) {
                float4 xv[4];
                #pragma unroll
                for (int i = 0; i < 4; ++i)
                    xv[i] = xs4[(t0 + i) * 64 + kt * 8 + k4];
                const float* xf = reinterpret_cast<const float*>(xv);
                #pragma unroll
                for (int kk = 0; kk < 4; ++kk) {
                    const float* wr = sm_wt + (k4 * 4 + kk) * W1_LD + d0;
                    u64 w0 = *reinterpret_cast<const u64*>(wr);
                    u64 w1 = *reinterpret_cast<const u64*>(wr + 2);
                    u64 w2 = *reinterpret_cast<const u64*>(wr + 4);
                    #pragma unroll
                    for (int i = 0; i < 4; ++i) {
                        u64 xx = bcast2(xf[i * 4 + kk]);
                        fma2(acc1[i][0], xx, w0);
                        fma2(acc1[i][1], xx, w1);
                        fma2(acc1[i][2], xx, w2);
                    }
                }
            }
        }
        // scatter q / k / v^T to SMEM
        #pragma unroll
        for (int i = 0; i < 4; ++i) {
            int t = t0 + i;
            #pragma unroll
            for (int p = 0; p < 3; ++p) {
                float v0 = lo32(acc1[i][p]);
                float v1 = hi32(acc1[i][p]);
                #pragma unroll
                for (int s = 0; s < 2; ++s) {
                    int c = d0 + 2 * p + s;
                    float v = s ? v1 : v0;
                    if (c < 32)       sm_q[t * QK_LD + c]         = v;
                    else if (c < 64)  sm_k[t * QK_LD + (c - 32)]  = v;
                    else              sm_vt[(c - 64) * VT_LD + t] = v;
                }
            }
        }
        __syncthreads();

        // ---- GEMM2: s[64,64] = q @ k^T (raw scores) ----
        {
            float acc2[4][4];
            #pragma unroll
            for (int i = 0; i < 4; ++i)
                #pragma unroll
                for (int j = 0; j < 4; ++j) acc2[i][j] = 0.f;
            const float4* q4 = reinterpret_cast<const float4*>(sm_q);
            const float4* k4 = reinterpret_cast<const float4*>(sm_k);
            #pragma unroll
            for (int kk4 = 0; kk4 < 8; ++kk4) {
                float4 qv[4], kv[4];
                #pragma unroll
                for (int i = 0; i < 4; ++i) qv[i] = q4[(t0 + i) * 9 + kk4];
                #pragma unroll
                for (int j = 0; j < 4; ++j) kv[j] = k4[(lg + j * 16) * 9 + kk4];
                const float* qf = reinterpret_cast<const float*>(qv);
                const float* kf = reinterpret_cast<const float*>(kv);
                #pragma unroll
                for (int kk = 0; kk < 4; ++kk)
                    #pragma unroll
                    for (int i = 0; i < 4; ++i)
                        #pragma unroll
                        for (int j = 0; j < 4; ++j)
                            acc2[i][j] += qf[i * 4 + kk] * kf[j * 4 + kk];
            }
            #pragma unroll
            for (int i = 0; i < 4; ++i)
                #pragma unroll
                for (int j = 0; j < 4; ++j)
                    sm_s[(t0 + i) * S_LD + lg + j * 16] = acc2[i][j];
        }
        __syncthreads();

        // ---- softmax over rows: p = exp(s*scale + bias - max); rinv = 1/sum ----
        {
            int row = tid >> 2;
            int qq  = tid & 3;
            int cb  = qq * 16;
            float vals[16];
            float mx = -1e30f;
            #pragma unroll
            for (int c = 0; c < 16; ++c) {
                int col = cb + c;
                float sc = sm_s[row * S_LD + col] * SCALE
                         + sm_rpe[(int)sm_idx[row * 64 + col] * 8 + h];
                vals[c] = sc;
                mx = fmaxf(mx, sc);
            }
            mx = fmaxf(mx, __shfl_xor_sync(0xFFFFFFFFu, mx, 1));
            mx = fmaxf(mx, __shfl_xor_sync(0xFFFFFFFFu, mx, 2));
            float sum = 0.f;
            #pragma unroll
            for (int c = 0; c < 16; ++c) {
                float e = __expf(vals[c] - mx);
                sm_s[row * S_LD + cb + c] = e;
                sum += e;
            }
            sum += __shfl_xor_sync(0xFFFFFFFFu, sum, 1);
            sum += __shfl_xor_sync(0xFFFFFFFFu, sum, 2);
            if (qq == 0) sm_rinv[row] = 1.f / sum;
        }
        __syncthreads();

        // ---- GEMM3: out_h[64,32] = p @ v  (v stored transposed) ----
        {
            float acc3[4][2];
            #pragma unroll
            for (int i = 0; i < 4; ++i) { acc3[i][0] = 0.f; acc3[i][1] = 0.f; }
            const float4* s4 = reinterpret_cast<const float4*>(sm_s);
            const float4* v4 = reinterpret_cast<const float4*>(sm_vt);
            #pragma unroll
            for (int m4 = 0; m4 < 16; ++m4) {
                float4 pv[4], vv[2];
                #pragma unroll
                for (int i = 0; i < 4; ++i) pv[i] = s4[(t0 + i) * 17 + m4];
                #pragma unroll
                for (int j = 0; j < 2; ++j) vv[j] = v4[(lg + j * 16) * 17 + m4];
                const float* pf = reinterpret_cast<const float*>(pv);
                const float* vf = reinterpret_cast<const float*>(vv);
                #pragma unroll
                for (int kk = 0; kk < 4; ++kk)
                    #pragma unroll
                    for (int i = 0; i < 4; ++i)
                        #pragma unroll
                        for (int j = 0; j < 2; ++j)
                            acc3[i][j] += pf[i * 4 + kk] * vf[j * 4 + kk];
            }
            #pragma unroll
            for (int i = 0; i < 4; ++i) {
                float rv = sm_rinv[t0 + i];
                #pragma unroll
                for (int j = 0; j < 2; ++j)
                    sm_op[(t0 + i) * OP_LD + h * 32 + lg + j * 16] = acc3[i][j] * rv;
            }
        }
        // next-head hazards covered by the sync at top of the GEMM1 kt-loop
    }

    // ================ GEMM4: y = out_pre @ Wproj^T, f32x2 packed ================
    {
        const float4* op4 = reinterpret_cast<const float4*>(sm_op);  // row = 65 float4
        float* yg = y + (size_t)win * (64 * 256);
        for (int half = 0; half < 2; ++half) {
            u64 acc4[4][4];
            #pragma unroll
            for (int i = 0; i < 4; ++i)
                #pragma unroll
                for (int p = 0; p < 4; ++p) acc4[i][p] = 0ull;

            for (int kt = 0; kt < 8; ++kt) {
                __syncthreads();
                // stage transposed Wproj tile: wt[kk][r], r in [0,128)
                #pragma unroll
                for (int i = 0; i < 16; ++i) {
                    int e = tid + i * 256;
                    int r = e >> 5, kk = e & 31;       // coalesced over kk
                    sm_wt[kk * W4_LD + r] =
                        Wproj[(half * 128 + r) * 256 + kt * 32 + kk];
                }
                __syncthreads();
                #pragma unroll
                for (int k4 = 0; k4 < 8; ++k4) {
                    float4 ov[4];
                    #pragma unroll
                    for (int i = 0; i < 4; ++i)
                        ov[i] = op4[(t0 + i) * 65 + kt * 8 + k4];
                    const float* of = reinterpret_cast<const float*>(ov);
                    #pragma unroll
                    for (int kk = 0; kk < 4; ++kk) {
                        const float* wr = sm_wt + (k4 * 4 + kk) * W4_LD + lg * 2;
                        u64 w[4];
                        #pragma unroll
                        for (int p = 0; p < 4; ++p)
                            w[p] = *reinterpret_cast<const u64*>(wr + p * 32);
                        #pragma unroll
                        for (int i = 0; i < 4; ++i) {
                            u64 xx = bcast2(of[i * 4 + kk]);
                            #pragma unroll
                            for (int p = 0; p < 4; ++p)
                                fma2(acc4[i][p], xx, w[p]);
                        }
                    }
                }
            }
            // cols = half*128 + p*32 + lg*2 (+1): coalesced float2 stores
            #pragma unroll
            for (int i = 0; i < 4; ++i)
                #pragma unroll
                for (int p = 0; p < 4; ++p) {
                    float2 v2 = make_float2(lo32(acc4[i][p]), hi32(acc4[i][p]));
                    *reinterpret_cast<float2*>(
                        yg + (t0 + i) * 256 + half * 128 + p * 32 + lg * 2) = v2;
                }
        }
    }
}

extern "C" void kernel_launch(void* const* d_in, const int* in_sizes, int n_in,
                              void* d_out, int out_size)
{
    const float* x     = (const float*)d_in[0];
    const float* Wqkv  = (const float*)d_in[1];
    const float* Wproj = (const float*)d_in[2];
    const float* rpe   = (const float*)d_in[3];
    const int*   ridx  = (const int*)d_in[4];
    float* y = (float*)d_out;

    cudaFuncSetAttribute(wmsa_fused_kernel,
                         cudaFuncAttributeMaxDynamicSharedMemorySize, SMEM_BYTES);
    wmsa_fused_kernel<<<4096, 256, SMEM_BYTES>>>(x, Wqkv, Wproj, rpe, ridx, y);
}